// round 10
// baseline (speedup 1.0000x reference)
#include <cuda_runtime.h>
#include <cuda_bf16.h>
#include <cstdint>

#define NN 10000
#define EE 320000
#define DD 256
#define D4 (DD / 4)
#define SLOTS 96   // deg ~ Poisson(32), P(>=96) < 1e-20

// -------- persistent device scratch (no allocations allowed) --------
__device__ __nv_bfloat16 g_hhi [NN * DD];
__device__ __nv_bfloat16 g_hlo [NN * DD];
__device__ __nv_bfloat16 g_h1hi[NN * DD];
__device__ __nv_bfloat16 g_h1lo[NN * DD];
__device__ __nv_bfloat16 g_w1hi[DD * DD];
__device__ __nv_bfloat16 g_w1lo[DD * DD];
__device__ __nv_bfloat16 g_w2hi[DD * DD];
__device__ __nv_bfloat16 g_w2lo[DD * DD];
__device__ int g_deg[NN];            // zero at load; re-zeroed by aggregate each call
__device__ int g_sorted[NN * SLOTS];

// ---------------- helpers ----------------
__device__ __forceinline__ uint32_t smem_u32(const void* p) {
    uint32_t a;
    asm("{ .reg .u64 t; cvta.to.shared.u64 t, %1; cvt.u32.u64 %0, t; }" : "=r"(a) : "l"(p));
    return a;
}
__device__ __forceinline__ void cp16(uint32_t s, const void* g) {
    asm volatile("cp.async.cg.shared.global [%0], [%1], 16;" :: "r"(s), "l"(g) : "memory");
}
#define CP_COMMIT() asm volatile("cp.async.commit_group;" ::: "memory")

#define LDSM4(R, A) \
    asm volatile("ldmatrix.sync.aligned.m8n8.x4.shared.b16 {%0,%1,%2,%3}, [%4];" \
        : "=r"((R)[0]), "=r"((R)[1]), "=r"((R)[2]), "=r"((R)[3]) : "r"(A))

#define MMA(D, A, B) \
    asm volatile("mma.sync.aligned.m16n8k16.row.col.f32.bf16.bf16.f32 " \
        "{%0,%1,%2,%3}, {%4,%5,%6,%7}, {%8,%9}, {%0,%1,%2,%3};" \
        : "+f"((D)[0]), "+f"((D)[1]), "+f"((D)[2]), "+f"((D)[3]) \
        : "r"((A)[0]), "r"((A)[1]), "r"((A)[2]), "r"((A)[3]), "r"((B)[0]), "r"((B)[1]))

__device__ __forceinline__ void bsplit(float v, __nv_bfloat16& hi, __nv_bfloat16& lo) {
    hi = __float2bfloat16(v);
    lo = __float2bfloat16(v - __bfloat162float(hi));
}

// SW128-style swizzle inside one 64-row x 128B tile: 16B unit XOR row%8
__device__ __forceinline__ uint32_t swz(int row, int unit) {
    return (uint32_t)(row * 128 + ((unit ^ (row & 7)) << 4));
}

// ------- fused prep: weight transpose/split + per-block dtype detect + scatter
__global__ void __launch_bounds__(256) prep_kernel(const float* __restrict__ W1,
                                                   const float* __restrict__ W2,
                                                   const int* __restrict__ ew) {
    const int tid = threadIdx.x;
    const int idx = blockIdx.x * 256 + tid;

    __shared__ int s_is64;
    if (tid < 32) {
        int bad = (ew[2 * tid + 1] != 0);
        unsigned m = __ballot_sync(0xffffffffu, bad);
        if (tid == 0) s_is64 = (m == 0) ? 1 : 0;
    }

    if (idx < 2 * DD * DD) {
        int layer = idx >> 16;
        int n = (idx >> 8) & 255;
        int k = idx & 255;
        const float* W = layer ? W2 : W1;
        float v = W[k * DD + n];
        __nv_bfloat16 hi, lo;
        bsplit(v, hi, lo);
        if (layer) { g_w2hi[n * DD + k] = hi; g_w2lo[n * DD + k] = lo; }
        else       { g_w1hi[n * DD + k] = hi; g_w1lo[n * DD + k] = lo; }
    }
    __syncthreads();

    const int f = s_is64;
    int src = f ? ew[2 * idx] : ew[idx];
    int dst = f ? ew[2 * (EE + idx)] : ew[EE + idx];
    int pos = atomicAdd(&g_deg[dst], 1);
    if (pos < SLOTS) g_sorted[dst * SLOTS + pos] = src;
}

// ---------------- aggregation -> bf16 hi/lo split; re-zeros g_deg ----------
__global__ void __launch_bounds__(64) aggregate_kernel(const float* __restrict__ x) {
    int node = blockIdx.x;
    int t = threadIdx.x;
    const float4* x4 = (const float4*)x;
    float4 acc = x4[(size_t)node * D4 + t];
    int deg = min(g_deg[node], SLOTS);
    int s = node * SLOTS;
    __shared__ int srcs[SLOTS];
    for (int k = t; k < deg; k += 64) srcs[k] = g_sorted[s + k];
    __syncthreads();
    if (t == 0) g_deg[node] = 0;
#pragma unroll 4
    for (int k = 0; k < deg; k++) {
        float4 v = x4[(size_t)srcs[k] * D4 + t];
        acc.x += v.x; acc.y += v.y; acc.z += v.z; acc.w += v.w;
    }
    __nv_bfloat16 h0, l0, h1, l1, h2, l2, h3, l3;
    bsplit(acc.x, h0, l0); bsplit(acc.y, h1, l1);
    bsplit(acc.z, h2, l2); bsplit(acc.w, h3, l3);
    uint2 uh, ul;
    uh.x = (uint32_t)__bfloat16_as_ushort(h0) | ((uint32_t)__bfloat16_as_ushort(h1) << 16);
    uh.y = (uint32_t)__bfloat16_as_ushort(h2) | ((uint32_t)__bfloat16_as_ushort(h3) << 16);
    ul.x = (uint32_t)__bfloat16_as_ushort(l0) | ((uint32_t)__bfloat16_as_ushort(l1) << 16);
    ul.y = (uint32_t)__bfloat16_as_ushort(l2) | ((uint32_t)__bfloat16_as_ushort(l3) << 16);
    *(uint2*)&g_hhi[(size_t)node * DD + 4 * t] = uh;
    *(uint2*)&g_hlo[(size_t)node * DD + 4 * t] = ul;
}

// ---------------- bf16-split HMMA GEMM, 3-stage pipeline ----------------
// CTA 64m x 64n, BK=32. Smem row = 128B packed [hi(64B) | lo(64B)], swizzled.
// Stage 16KB, 3 stages, 4 CTAs/SM, one barrier/iter.
// MMA ordering: grouped BY SPLIT TERM so consecutive writes to the same
// accumulator are separated by 3 independent HMMAs (hides accum latency).
#define STAGE_B 16384
#define NSTG 3
#define SMEM_BYTES (NSTG * STAGE_B + 256)

template <int LAYER>
__global__ void __launch_bounds__(256, 4) gemm_mma(const float* __restrict__ bias,
                                                   float* __restrict__ out) {
    extern __shared__ char smem[];
    const uint32_t sb = smem_u32(smem);
    const int tid = threadIdx.x, wid = tid >> 5, lane = tid & 31;
    const int m0 = blockIdx.x * 64, n0 = blockIdx.y * 64;
    const int wm = wid >> 2, wn = wid & 3;   // 2m x 4n warps

    const __nv_bfloat16* __restrict__ Ahi = (LAYER == 1) ? g_hhi  : g_h1hi;
    const __nv_bfloat16* __restrict__ Alo = (LAYER == 1) ? g_hlo  : g_h1lo;
    const __nv_bfloat16* __restrict__ Bhi = (LAYER == 1) ? g_w1hi : g_w2hi;
    const __nv_bfloat16* __restrict__ Blo = (LAYER == 1) ? g_w1lo : g_w2lo;

    float* sBias = (float*)(smem + NSTG * STAGE_B);
    if (tid < 64) sBias[tid] = bias[n0 + tid];

    const int row = tid >> 2, seg = tid & 3;
    const int gma = min(m0 + row, NN - 1);
    const uint32_t sA0 = swz(row, seg), sA1 = swz(row, seg + 4);

    auto load_stage = [&](int kb, uint32_t st) {
        size_t goa = (size_t)gma * DD + kb * 32 + seg * 8;
        cp16(st + sA0, Ahi + goa);
        cp16(st + sA1, Alo + goa);
        size_t gob = (size_t)(n0 + row) * DD + kb * 32 + seg * 8;
        cp16(st + 8192 + sA0, Bhi + gob);
        cp16(st + 8192 + sA1, Blo + gob);
        CP_COMMIT();
    };

    float acc[2][2][4];
#pragma unroll
    for (int a = 0; a < 2; a++)
#pragma unroll
        for (int b = 0; b < 2; b++)
#pragma unroll
            for (int c = 0; c < 4; c++) acc[a][b][c] = 0.f;

    load_stage(0, sb);
    load_stage(1, sb + STAGE_B);

    const int bg = lane >> 3;
    const int la15 = lane & 15, la16 = lane >> 4;
    const int rB = wn * 16 + ((bg >> 1) << 3) + (lane & 7);

    for (int kb = 0; kb < 8; kb++) {
        uint32_t st = sb + (kb % NSTG) * STAGE_B;
        if (kb < 6) asm volatile("cp.async.wait_group 1;" ::: "memory");
        else        asm volatile("cp.async.wait_group 0;" ::: "memory");
        __syncthreads();   // publish stage kb; also gates slot reuse below
        if (kb + 2 < 8) load_stage(kb + 2, sb + ((kb + 2) % NSTG) * STAGE_B);
#pragma unroll
        for (int ks = 0; ks < 2; ks++) {
            uint32_t ah[2][4], al[2][4], bh[4], bl[4];
            const int ua = ks * 2 + la16;
#pragma unroll
            for (int mt = 0; mt < 2; mt++) {
                int r = wm * 32 + mt * 16 + la15;
                LDSM4(ah[mt], st + swz(r, ua));
                LDSM4(al[mt], st + swz(r, ua + 4));
            }
            const int ub = ks * 2 + (bg & 1);
            LDSM4(bh, st + 8192 + swz(rB, ub));
            LDSM4(bl, st + 8192 + swz(rB, ub + 4));
            // term 1: Ah*Bh — 4 independent MMAs
#pragma unroll
            for (int mt = 0; mt < 2; mt++)
#pragma unroll
                for (int nt = 0; nt < 2; nt++)
                    MMA(acc[mt][nt], ah[mt], (&bh[nt * 2]));
            // term 2: Ah*Bl — same accs, 4 apart from their last write
#pragma unroll
            for (int mt = 0; mt < 2; mt++)
#pragma unroll
                for (int nt = 0; nt < 2; nt++)
                    MMA(acc[mt][nt], ah[mt], (&bl[nt * 2]));
            // term 3: Al*Bh
#pragma unroll
            for (int mt = 0; mt < 2; mt++)
#pragma unroll
                for (int nt = 0; nt < 2; nt++)
                    MMA(acc[mt][nt], al[mt], (&bh[nt * 2]));
        }
    }

    const int gq = lane >> 2, tq = lane & 3;
#pragma unroll
    for (int mt = 0; mt < 2; mt++) {
#pragma unroll
        for (int half = 0; half < 2; half++) {
            int r = m0 + wm * 32 + mt * 16 + gq + half * 8;
            if (r >= NN) continue;
#pragma unroll
            for (int nt = 0; nt < 2; nt++) {
                int col = wn * 16 + nt * 8 + tq * 2;
                float v0 = acc[mt][nt][half * 2 + 0] + sBias[col];
                float v1 = acc[mt][nt][half * 2 + 1] + sBias[col + 1];
                size_t o = (size_t)r * DD + n0 + col;
                if (LAYER == 1) {
                    v0 = fmaxf(v0, 0.f);
                    v1 = fmaxf(v1, 0.f);
                    __nv_bfloat16 h0, l0, h1, l1;
                    bsplit(v0, h0, l0);
                    bsplit(v1, h1, l1);
                    *(uint32_t*)&g_h1hi[o] =
                        (uint32_t)__bfloat16_as_ushort(h0) | ((uint32_t)__bfloat16_as_ushort(h1) << 16);
                    *(uint32_t*)&g_h1lo[o] =
                        (uint32_t)__bfloat16_as_ushort(l0) | ((uint32_t)__bfloat16_as_ushort(l1) << 16);
                } else {
                    *(float2*)(out + o) = make_float2(v0, v1);
                }
            }
        }
    }
}

extern "C" void kernel_launch(void* const* d_in, const int* in_sizes, int n_in,
                              void* d_out, int out_size) {
    const float* x  = (const float*)d_in[0];
    const int*   ei = (const int*)d_in[1];
    const float* W1 = (const float*)d_in[2];
    const float* b1 = (const float*)d_in[3];
    const float* W2 = (const float*)d_in[4];
    const float* b2 = (const float*)d_in[5];
    float* out = (float*)d_out;

    cudaFuncSetAttribute(gemm_mma<1>, cudaFuncAttributeMaxDynamicSharedMemorySize, SMEM_BYTES);
    cudaFuncSetAttribute(gemm_mma<2>, cudaFuncAttributeMaxDynamicSharedMemorySize, SMEM_BYTES);

    prep_kernel<<<EE / 256, 256>>>(W1, W2, ei);
    aggregate_kernel<<<NN, 64>>>(x);

    dim3 grid((NN + 63) / 64, DD / 64);
    gemm_mma<1><<<grid, 256, SMEM_BYTES>>>(b1, out);
    gemm_mma<2><<<grid, 256, SMEM_BYTES>>>(b2, out);
}

// round 11
// speedup vs baseline: 1.0401x; 1.0401x over previous
#include <cuda_runtime.h>
#include <cuda_bf16.h>
#include <cstdint>

#define NN 10000
#define EE 320000
#define DD 256
#define D4 (DD / 4)
#define SLOTS 96   // deg ~ Poisson(32), P(>=96) < 1e-20

// -------- persistent device scratch (no allocations allowed) --------
__device__ __nv_bfloat16 g_hhi [NN * DD];
__device__ __nv_bfloat16 g_hlo [NN * DD];
__device__ __nv_bfloat16 g_h1hi[NN * DD];
__device__ __nv_bfloat16 g_h1lo[NN * DD];
__device__ __nv_bfloat16 g_w1hi[DD * DD];
__device__ __nv_bfloat16 g_w1lo[DD * DD];
__device__ __nv_bfloat16 g_w2hi[DD * DD];
__device__ __nv_bfloat16 g_w2lo[DD * DD];
__device__ int g_deg[NN];            // zero at load; re-zeroed by aggregate each call
__device__ int g_sorted[NN * SLOTS];

// ---------------- helpers ----------------
__device__ __forceinline__ uint32_t smem_u32(const void* p) {
    uint32_t a;
    asm("{ .reg .u64 t; cvta.to.shared.u64 t, %1; cvt.u32.u64 %0, t; }" : "=r"(a) : "l"(p));
    return a;
}
__device__ __forceinline__ void cp16(uint32_t s, const void* g) {
    asm volatile("cp.async.cg.shared.global [%0], [%1], 16;" :: "r"(s), "l"(g) : "memory");
}
#define CP_COMMIT() asm volatile("cp.async.commit_group;" ::: "memory")

#define LDSM4(R, A) \
    asm volatile("ldmatrix.sync.aligned.m8n8.x4.shared.b16 {%0,%1,%2,%3}, [%4];" \
        : "=r"((R)[0]), "=r"((R)[1]), "=r"((R)[2]), "=r"((R)[3]) : "r"(A))

#define MMA(D, A, B) \
    asm volatile("mma.sync.aligned.m16n8k16.row.col.f32.bf16.bf16.f32 " \
        "{%0,%1,%2,%3}, {%4,%5,%6,%7}, {%8,%9}, {%0,%1,%2,%3};" \
        : "+f"((D)[0]), "+f"((D)[1]), "+f"((D)[2]), "+f"((D)[3]) \
        : "r"((A)[0]), "r"((A)[1]), "r"((A)[2]), "r"((A)[3]), "r"((B)[0]), "r"((B)[1]))

__device__ __forceinline__ void bsplit(float v, __nv_bfloat16& hi, __nv_bfloat16& lo) {
    hi = __float2bfloat16(v);
    lo = __float2bfloat16(v - __bfloat162float(hi));
}

// SW128-style swizzle inside one 64-row x 128B tile: 16B unit XOR row%8
__device__ __forceinline__ uint32_t swz(int row, int unit) {
    return (uint32_t)(row * 128 + ((unit ^ (row & 7)) << 4));
}

// ------- fused prep: weight transpose/split + per-block dtype detect + scatter
__global__ void __launch_bounds__(256) prep_kernel(const float* __restrict__ W1,
                                                   const float* __restrict__ W2,
                                                   const int* __restrict__ ew) {
    const int tid = threadIdx.x;
    const int idx = blockIdx.x * 256 + tid;

    __shared__ int s_is64;
    if (tid < 32) {
        int bad = (ew[2 * tid + 1] != 0);
        unsigned m = __ballot_sync(0xffffffffu, bad);
        if (tid == 0) s_is64 = (m == 0) ? 1 : 0;
    }

    if (idx < 2 * DD * DD) {
        int layer = idx >> 16;
        int n = (idx >> 8) & 255;
        int k = idx & 255;
        const float* W = layer ? W2 : W1;
        float v = W[k * DD + n];
        __nv_bfloat16 hi, lo;
        bsplit(v, hi, lo);
        if (layer) { g_w2hi[n * DD + k] = hi; g_w2lo[n * DD + k] = lo; }
        else       { g_w1hi[n * DD + k] = hi; g_w1lo[n * DD + k] = lo; }
    }
    __syncthreads();

    const int f = s_is64;
    int src = f ? ew[2 * idx] : ew[idx];
    int dst = f ? ew[2 * (EE + idx)] : ew[EE + idx];
    int pos = atomicAdd(&g_deg[dst], 1);
    if (pos < SLOTS) g_sorted[dst * SLOTS + pos] = src;
}

// ---------------- aggregation -> bf16 hi/lo split; re-zeros g_deg ----------
__global__ void __launch_bounds__(64) aggregate_kernel(const float* __restrict__ x) {
    int node = blockIdx.x;
    int t = threadIdx.x;
    const float4* x4 = (const float4*)x;
    float4 acc = x4[(size_t)node * D4 + t];
    int deg = min(g_deg[node], SLOTS);
    int s = node * SLOTS;
    __shared__ int srcs[SLOTS];
    for (int k = t; k < deg; k += 64) srcs[k] = g_sorted[s + k];
    __syncthreads();
    if (t == 0) g_deg[node] = 0;
#pragma unroll 4
    for (int k = 0; k < deg; k++) {
        float4 v = x4[(size_t)srcs[k] * D4 + t];
        acc.x += v.x; acc.y += v.y; acc.z += v.z; acc.w += v.w;
    }
    __nv_bfloat16 h0, l0, h1, l1, h2, l2, h3, l3;
    bsplit(acc.x, h0, l0); bsplit(acc.y, h1, l1);
    bsplit(acc.z, h2, l2); bsplit(acc.w, h3, l3);
    uint2 uh, ul;
    uh.x = (uint32_t)__bfloat16_as_ushort(h0) | ((uint32_t)__bfloat16_as_ushort(h1) << 16);
    uh.y = (uint32_t)__bfloat16_as_ushort(h2) | ((uint32_t)__bfloat16_as_ushort(h3) << 16);
    ul.x = (uint32_t)__bfloat16_as_ushort(l0) | ((uint32_t)__bfloat16_as_ushort(l1) << 16);
    ul.y = (uint32_t)__bfloat16_as_ushort(l2) | ((uint32_t)__bfloat16_as_ushort(l3) << 16);
    *(uint2*)&g_hhi[(size_t)node * DD + 4 * t] = uh;
    *(uint2*)&g_hlo[(size_t)node * DD + 4 * t] = ul;
}

// ---------------- bf16-split HMMA GEMM, 3-stage + fragment pipeline --------
// CTA 64m x 64n, BK=32, 3 smem stages (16KB each). NEW: register-level
// fragment double-buffer — the 6 LDSM for phase p+1 are issued before the
// 12 MMAs of phase p, hiding the ~30cy LDSM latency behind MMA issue.
// One barrier per k-iter (slot-reuse invariant: last read of stage s is in
// iter s's ks0 segment; its slot is overwritten after the iter-s barrier).
#define STAGE_B 16384
#define NSTG 3
#define SMEM_BYTES (NSTG * STAGE_B + 256)

template <int LAYER>
__global__ void __launch_bounds__(256, 3) gemm_mma(const float* __restrict__ bias,
                                                   float* __restrict__ out) {
    extern __shared__ char smem[];
    const uint32_t sb = smem_u32(smem);
    const int tid = threadIdx.x, wid = tid >> 5, lane = tid & 31;
    const int m0 = blockIdx.x * 64, n0 = blockIdx.y * 64;
    const int wm = wid >> 2, wn = wid & 3;   // 2m x 4n warps

    const __nv_bfloat16* __restrict__ Ahi = (LAYER == 1) ? g_hhi  : g_h1hi;
    const __nv_bfloat16* __restrict__ Alo = (LAYER == 1) ? g_hlo  : g_h1lo;
    const __nv_bfloat16* __restrict__ Bhi = (LAYER == 1) ? g_w1hi : g_w2hi;
    const __nv_bfloat16* __restrict__ Blo = (LAYER == 1) ? g_w1lo : g_w2lo;

    float* sBias = (float*)(smem + NSTG * STAGE_B);
    if (tid < 64) sBias[tid] = bias[n0 + tid];

    const int row = tid >> 2, seg = tid & 3;
    const int gma = min(m0 + row, NN - 1);
    const uint32_t sA0 = swz(row, seg), sA1 = swz(row, seg + 4);

    auto load_stage = [&](int kb, uint32_t st) {
        size_t goa = (size_t)gma * DD + kb * 32 + seg * 8;
        cp16(st + sA0, Ahi + goa);
        cp16(st + sA1, Alo + goa);
        size_t gob = (size_t)(n0 + row) * DD + kb * 32 + seg * 8;
        cp16(st + 8192 + sA0, Bhi + gob);
        cp16(st + 8192 + sA1, Blo + gob);
        CP_COMMIT();
    };

    float acc[2][2][4];
#pragma unroll
    for (int a = 0; a < 2; a++)
#pragma unroll
        for (int b = 0; b < 2; b++)
#pragma unroll
            for (int c = 0; c < 4; c++) acc[a][b][c] = 0.f;

    const int bg = lane >> 3;
    const int la15 = lane & 15, la16 = lane >> 4;
    const int rA0 = wm * 32 + la15, rA1 = wm * 32 + 16 + la15;
    const int rB = wn * 16 + ((bg >> 1) << 3) + (lane & 7);

    // double-buffered fragments
    uint32_t AH[2][2][4], AL[2][2][4], BH[2][4], BL[2][4];

    auto ld_frags = [&](int buf, uint32_t st, int ks) {
        const int ua = ks * 2 + la16;
        LDSM4(AH[buf][0], st + swz(rA0, ua));
        LDSM4(AL[buf][0], st + swz(rA0, ua + 4));
        LDSM4(AH[buf][1], st + swz(rA1, ua));
        LDSM4(AL[buf][1], st + swz(rA1, ua + 4));
        const int ub = ks * 2 + (bg & 1);
        LDSM4(BH[buf], st + 8192 + swz(rB, ub));
        LDSM4(BL[buf], st + 8192 + swz(rB, ub + 4));
    };
    auto do_mma = [&](int buf) {
#pragma unroll
        for (int mt = 0; mt < 2; mt++)
#pragma unroll
            for (int nt = 0; nt < 2; nt++)
                MMA(acc[mt][nt], AH[buf][mt], (&BH[buf][nt * 2]));
#pragma unroll
        for (int mt = 0; mt < 2; mt++)
#pragma unroll
            for (int nt = 0; nt < 2; nt++)
                MMA(acc[mt][nt], AH[buf][mt], (&BL[buf][nt * 2]));
#pragma unroll
        for (int mt = 0; mt < 2; mt++)
#pragma unroll
            for (int nt = 0; nt < 2; nt++)
                MMA(acc[mt][nt], AL[buf][mt], (&BH[buf][nt * 2]));
    };

    load_stage(0, sb);
    load_stage(1, sb + STAGE_B);
    asm volatile("cp.async.wait_group 1;" ::: "memory");   // stage 0 ready
    __syncthreads();
    ld_frags(0, sb, 0);
    int cur = 0;

#pragma unroll
    for (int kb = 0; kb < 8; kb++) {
        uint32_t st = sb + (kb % NSTG) * STAGE_B;
        // ---- ks = 0 segment: issue next gmem stage, prefetch ks=1 frags
        if (kb + 2 < 8) load_stage(kb + 2, sb + ((kb + 2) % NSTG) * STAGE_B);
        ld_frags(cur ^ 1, st, 1);
        do_mma(cur);
        cur ^= 1;
        // ---- ks = 1 segment: make stage kb+1 visible, prefetch its ks=0 frags
        if (kb < 7) {
            if (kb < 6) asm volatile("cp.async.wait_group 1;" ::: "memory");
            else        asm volatile("cp.async.wait_group 0;" ::: "memory");
            __syncthreads();   // publish stage kb+1; gates slot reuse
            ld_frags(cur ^ 1, sb + ((kb + 1) % NSTG) * STAGE_B, 0);
        }
        do_mma(cur);
        cur ^= 1;
    }

    const int gq = lane >> 2, tq = lane & 3;
#pragma unroll
    for (int mt = 0; mt < 2; mt++) {
#pragma unroll
        for (int half = 0; half < 2; half++) {
            int r = m0 + wm * 32 + mt * 16 + gq + half * 8;
            if (r >= NN) continue;
#pragma unroll
            for (int nt = 0; nt < 2; nt++) {
                int col = wn * 16 + nt * 8 + tq * 2;
                float v0 = acc[mt][nt][half * 2 + 0] + sBias[col];
                float v1 = acc[mt][nt][half * 2 + 1] + sBias[col + 1];
                size_t o = (size_t)r * DD + n0 + col;
                if (LAYER == 1) {
                    v0 = fmaxf(v0, 0.f);
                    v1 = fmaxf(v1, 0.f);
                    __nv_bfloat16 h0, l0, h1, l1;
                    bsplit(v0, h0, l0);
                    bsplit(v1, h1, l1);
                    *(uint32_t*)&g_h1hi[o] =
                        (uint32_t)__bfloat16_as_ushort(h0) | ((uint32_t)__bfloat16_as_ushort(h1) << 16);
                    *(uint32_t*)&g_h1lo[o] =
                        (uint32_t)__bfloat16_as_ushort(l0) | ((uint32_t)__bfloat16_as_ushort(l1) << 16);
                } else {
                    *(float2*)(out + o) = make_float2(v0, v1);
                }
            }
        }
    }
}

extern "C" void kernel_launch(void* const* d_in, const int* in_sizes, int n_in,
                              void* d_out, int out_size) {
    const float* x  = (const float*)d_in[0];
    const int*   ei = (const int*)d_in[1];
    const float* W1 = (const float*)d_in[2];
    const float* b1 = (const float*)d_in[3];
    const float* W2 = (const float*)d_in[4];
    const float* b2 = (const float*)d_in[5];
    float* out = (float*)d_out;

    cudaFuncSetAttribute(gemm_mma<1>, cudaFuncAttributeMaxDynamicSharedMemorySize, SMEM_BYTES);
    cudaFuncSetAttribute(gemm_mma<2>, cudaFuncAttributeMaxDynamicSharedMemorySize, SMEM_BYTES);

    prep_kernel<<<EE / 256, 256>>>(W1, W2, ei);
    aggregate_kernel<<<NN, 64>>>(x);

    dim3 grid((NN + 63) / 64, DD / 64);
    gemm_mma<1><<<grid, 256, SMEM_BYTES>>>(b1, out);
    gemm_mma<2><<<grid, 256, SMEM_BYTES>>>(b2, out);
}

// round 12
// speedup vs baseline: 1.1892x; 1.1434x over previous
#include <cuda_runtime.h>
#include <cuda_fp16.h>
#include <cstdint>

#define NN 10000
#define EE 320000
#define DD 256
#define D4 (DD / 4)
#define SLOTS 96   // deg ~ Poisson(32), P(>=96) < 1e-20

// -------- persistent device scratch (no allocations allowed) --------
__device__ __half g_h  [NN * DD];   // fp16(x+agg)
__device__ __half g_h1 [NN * DD];   // fp16(relu(h@W1+b1))
__device__ __half g_w1h[DD * DD];   // W1^T hi
__device__ __half g_w1l[DD * DD];   // W1^T lo * 2048
__device__ __half g_w2h[DD * DD];
__device__ __half g_w2l[DD * DD];
__device__ int g_deg[NN];           // zero at load; re-zeroed by aggregate each call
__device__ int g_sorted[NN * SLOTS];

// ---------------- helpers ----------------
__device__ __forceinline__ uint32_t smem_u32(const void* p) {
    uint32_t a;
    asm("{ .reg .u64 t; cvta.to.shared.u64 t, %1; cvt.u32.u64 %0, t; }" : "=r"(a) : "l"(p));
    return a;
}
__device__ __forceinline__ void cp16(uint32_t s, const void* g) {
    asm volatile("cp.async.cg.shared.global [%0], [%1], 16;" :: "r"(s), "l"(g) : "memory");
}
#define CP_COMMIT() asm volatile("cp.async.commit_group;" ::: "memory")

#define LDSM4(R, A) \
    asm volatile("ldmatrix.sync.aligned.m8n8.x4.shared.b16 {%0,%1,%2,%3}, [%4];" \
        : "=r"((R)[0]), "=r"((R)[1]), "=r"((R)[2]), "=r"((R)[3]) : "r"(A))

#define MMAH(D, A, B) \
    asm volatile("mma.sync.aligned.m16n8k16.row.col.f32.f16.f16.f32 " \
        "{%0,%1,%2,%3}, {%4,%5,%6,%7}, {%8,%9}, {%0,%1,%2,%3};" \
        : "+f"((D)[0]), "+f"((D)[1]), "+f"((D)[2]), "+f"((D)[3]) \
        : "r"((A)[0]), "r"((A)[1]), "r"((A)[2]), "r"((A)[3]), "r"((B)[0]), "r"((B)[1]))

// B-weight split: w = Bh + Bl/2048, Bl kept in fp16 normal range
__device__ __forceinline__ void wsplit(float v, __half& hi, __half& lo) {
    hi = __float2half(v);
    lo = __float2half((v - __half2float(hi)) * 2048.0f);
}

// SW128-style swizzle inside a 64-row x 128B tile: 16B unit XOR row%8 (B tile)
__device__ __forceinline__ uint32_t swz(int row, int unit) {
    return (uint32_t)(row * 128 + ((unit ^ (row & 7)) << 4));
}

// ------- fused prep: weight transpose/split + per-block dtype detect + scatter
__global__ void __launch_bounds__(256) prep_kernel(const float* __restrict__ W1,
                                                   const float* __restrict__ W2,
                                                   const int* __restrict__ ew) {
    const int tid = threadIdx.x;
    const int idx = blockIdx.x * 256 + tid;

    __shared__ int s_is64;
    if (tid < 32) {
        int bad = (ew[2 * tid + 1] != 0);
        unsigned m = __ballot_sync(0xffffffffu, bad);
        if (tid == 0) s_is64 = (m == 0) ? 1 : 0;
    }

    if (idx < 2 * DD * DD) {
        int layer = idx >> 16;
        int n = (idx >> 8) & 255;
        int k = idx & 255;
        const float* W = layer ? W2 : W1;
        float v = W[k * DD + n];
        __half hi, lo;
        wsplit(v, hi, lo);
        if (layer) { g_w2h[n * DD + k] = hi; g_w2l[n * DD + k] = lo; }
        else       { g_w1h[n * DD + k] = hi; g_w1l[n * DD + k] = lo; }
    }
    __syncthreads();

    const int f = s_is64;
    int src = f ? ew[2 * idx] : ew[idx];
    int dst = f ? ew[2 * (EE + idx)] : ew[EE + idx];
    int pos = atomicAdd(&g_deg[dst], 1);
    if (pos < SLOTS) g_sorted[dst * SLOTS + pos] = src;
}

// ---------------- aggregation -> fp16; re-zeros g_deg ----------------
__global__ void __launch_bounds__(64) aggregate_kernel(const float* __restrict__ x) {
    int node = blockIdx.x;
    int t = threadIdx.x;
    const float4* x4 = (const float4*)x;
    float4 acc = x4[(size_t)node * D4 + t];
    int deg = min(g_deg[node], SLOTS);
    int s = node * SLOTS;
    __shared__ int srcs[SLOTS];
    for (int k = t; k < deg; k += 64) srcs[k] = g_sorted[s + k];
    __syncthreads();
    if (t == 0) g_deg[node] = 0;
#pragma unroll 4
    for (int k = 0; k < deg; k++) {
        float4 v = x4[(size_t)srcs[k] * D4 + t];
        acc.x += v.x; acc.y += v.y; acc.z += v.z; acc.w += v.w;
    }
    __half h0 = __float2half(acc.x), h1 = __float2half(acc.y);
    __half h2 = __float2half(acc.z), h3 = __float2half(acc.w);
    uint2 u;
    u.x = (uint32_t)__half_as_ushort(h0) | ((uint32_t)__half_as_ushort(h1) << 16);
    u.y = (uint32_t)__half_as_ushort(h2) | ((uint32_t)__half_as_ushort(h3) << 16);
    *(uint2*)&g_h[(size_t)node * DD + 4 * t] = u;
}

// ---------------- fp16 2-term HMMA GEMM, 3-stage + fragment pipeline -------
// C = A@(Bh + Bl/2048) + bias. A unsplit fp16; Bl-term goes to a separate
// fp32 accumulator, folded in the epilogue. 8 MMA + 4 LDSM per phase.
// A tile: 64 rows x 64B, 80B stride (conflict-free: r*80 mod 128 cycles all
// eight 16B units). B tile: 128B rows [Bh 64B | Bl 64B], XOR swizzle.
// Stage = 5120 + 8192 = 13312B; 3 stages; one barrier per k-iter.
#define A_BYTES 5120
#define STAGE_B 13312
#define NSTG 3
#define SMEM_BYTES (NSTG * STAGE_B + 256)

template <int LAYER>
__global__ void __launch_bounds__(256, 3) gemm_mma(const float* __restrict__ bias,
                                                   float* __restrict__ out) {
    extern __shared__ char smem[];
    const uint32_t sb = smem_u32(smem);
    const int tid = threadIdx.x, wid = tid >> 5, lane = tid & 31;
    const int m0 = blockIdx.x * 64, n0 = blockIdx.y * 64;
    const int wm = wid >> 2, wn = wid & 3;   // 2m x 4n warps

    const __half* __restrict__ A  = (LAYER == 1) ? g_h   : g_h1;
    const __half* __restrict__ Bh = (LAYER == 1) ? g_w1h : g_w2h;
    const __half* __restrict__ Bl = (LAYER == 1) ? g_w1l : g_w2l;

    float* sBias = (float*)(smem + NSTG * STAGE_B);
    if (tid < 64) sBias[tid] = bias[n0 + tid];

    const int row = tid >> 2, seg = tid & 3;
    const int gma = min(m0 + row, NN - 1);
    const uint32_t sBs = swz(row, seg), sBs4 = swz(row, seg + 4);

    auto load_stage = [&](int kb, uint32_t st) {
        size_t goa = (size_t)gma * DD + kb * 32 + seg * 8;
        cp16(st + row * 80 + seg * 16, A + goa);
        size_t gob = (size_t)(n0 + row) * DD + kb * 32 + seg * 8;
        cp16(st + A_BYTES + sBs,  Bh + gob);
        cp16(st + A_BYTES + sBs4, Bl + gob);
        CP_COMMIT();
    };

    float acc[2][2][4], acc2[2][2][4];
#pragma unroll
    for (int a = 0; a < 2; a++)
#pragma unroll
        for (int b = 0; b < 2; b++)
#pragma unroll
            for (int c = 0; c < 4; c++) { acc[a][b][c] = 0.f; acc2[a][b][c] = 0.f; }

    const int bg = lane >> 3;
    const int la15 = lane & 15, la16 = lane >> 4;
    const int rA0 = wm * 32 + la15, rA1 = wm * 32 + 16 + la15;
    const int rB = wn * 16 + ((bg >> 1) << 3) + (lane & 7);

    uint32_t AH[2][2][4], BHf[2][4], BLf[2][4];

    auto ld_frags = [&](int buf, uint32_t st, int ks) {
        LDSM4(AH[buf][0], st + rA0 * 80 + ks * 32 + la16 * 16);
        LDSM4(AH[buf][1], st + rA1 * 80 + ks * 32 + la16 * 16);
        const int ub = ks * 2 + (bg & 1);
        LDSM4(BHf[buf], st + A_BYTES + swz(rB, ub));
        LDSM4(BLf[buf], st + A_BYTES + swz(rB, ub + 4));
    };
    auto do_mma = [&](int buf) {
#pragma unroll
        for (int mt = 0; mt < 2; mt++)
#pragma unroll
            for (int nt = 0; nt < 2; nt++)
                MMAH(acc[mt][nt], AH[buf][mt], (&BHf[buf][nt * 2]));
#pragma unroll
        for (int mt = 0; mt < 2; mt++)
#pragma unroll
            for (int nt = 0; nt < 2; nt++)
                MMAH(acc2[mt][nt], AH[buf][mt], (&BLf[buf][nt * 2]));
    };

    load_stage(0, sb);
    load_stage(1, sb + STAGE_B);
    asm volatile("cp.async.wait_group 1;" ::: "memory");   // stage 0 ready
    __syncthreads();
    ld_frags(0, sb, 0);
    int cur = 0;

#pragma unroll
    for (int kb = 0; kb < 8; kb++) {
        uint32_t st = sb + (kb % NSTG) * STAGE_B;
        // ---- ks = 0 segment: issue next gmem stage, prefetch ks=1 frags
        if (kb + 2 < 8) load_stage(kb + 2, sb + ((kb + 2) % NSTG) * STAGE_B);
        ld_frags(cur ^ 1, st, 1);
        do_mma(cur);
        cur ^= 1;
        // ---- ks = 1 segment: make stage kb+1 visible, prefetch its ks=0 frags
        if (kb < 7) {
            if (kb < 6) asm volatile("cp.async.wait_group 1;" ::: "memory");
            else        asm volatile("cp.async.wait_group 0;" ::: "memory");
            __syncthreads();   // publish stage kb+1; gates slot reuse
            ld_frags(cur ^ 1, sb + ((kb + 1) % NSTG) * STAGE_B, 0);
        }
        do_mma(cur);
        cur ^= 1;
    }

    const float SC = 1.0f / 2048.0f;
    const int gq = lane >> 2, tq = lane & 3;
#pragma unroll
    for (int mt = 0; mt < 2; mt++) {
#pragma unroll
        for (int half = 0; half < 2; half++) {
            int r = m0 + wm * 32 + mt * 16 + gq + half * 8;
            if (r >= NN) continue;
#pragma unroll
            for (int nt = 0; nt < 2; nt++) {
                int col = wn * 16 + nt * 8 + tq * 2;
                int i0 = half * 2;
                float v0 = acc[mt][nt][i0]     + acc2[mt][nt][i0]     * SC + sBias[col];
                float v1 = acc[mt][nt][i0 + 1] + acc2[mt][nt][i0 + 1] * SC + sBias[col + 1];
                size_t o = (size_t)r * DD + n0 + col;
                if (LAYER == 1) {
                    v0 = fmaxf(v0, 0.f);
                    v1 = fmaxf(v1, 0.f);
                    __half p0 = __float2half(v0), p1 = __float2half(v1);
                    *(uint32_t*)&g_h1[o] =
                        (uint32_t)__half_as_ushort(p0) | ((uint32_t)__half_as_ushort(p1) << 16);
                } else {
                    *(float2*)(out + o) = make_float2(v0, v1);
                }
            }
        }
    }
}

extern "C" void kernel_launch(void* const* d_in, const int* in_sizes, int n_in,
                              void* d_out, int out_size) {
    const float* x  = (const float*)d_in[0];
    const int*   ei = (const int*)d_in[1];
    const float* W1 = (const float*)d_in[2];
    const float* b1 = (const float*)d_in[3];
    const float* W2 = (const float*)d_in[4];
    const float* b2 = (const float*)d_in[5];
    float* out = (float*)d_out;

    cudaFuncSetAttribute(gemm_mma<1>, cudaFuncAttributeMaxDynamicSharedMemorySize, SMEM_BYTES);
    cudaFuncSetAttribute(gemm_mma<2>, cudaFuncAttributeMaxDynamicSharedMemorySize, SMEM_BYTES);

    prep_kernel<<<EE / 256, 256>>>(W1, W2, ei);
    aggregate_kernel<<<NN, 64>>>(x);

    dim3 grid((NN + 63) / 64, DD / 64);
    gemm_mma<1><<<grid, 256, SMEM_BYTES>>>(b1, out);
    gemm_mma<2><<<grid, 256, SMEM_BYTES>>>(b2, out);
}

// round 13
// speedup vs baseline: 1.2880x; 1.0831x over previous
#include <cuda_runtime.h>
#include <cuda_fp16.h>
#include <cstdint>

#define NN 10000
#define EE 320000
#define DD 256
#define D4 (DD / 4)
#define SLOTS 96   // deg ~ Poisson(32), P(>=96) < 1e-20

// -------- persistent device scratch (no allocations allowed) --------
__device__ __half g_xh [NN * DD];   // fp16(x) — gather source (5MB, L2-resident)
__device__ __half g_h  [NN * DD];   // fp16(x+agg)
__device__ __half g_h1 [NN * DD];   // fp16(relu(h@W1+b1))
__device__ __half g_w1h[DD * DD];   // W1^T hi
__device__ __half g_w1l[DD * DD];   // W1^T lo * 2048
__device__ __half g_w2h[DD * DD];
__device__ __half g_w2l[DD * DD];
__device__ int g_deg[NN];           // zero at load; re-zeroed by aggregate each call
__device__ int g_sorted[NN * SLOTS];

// ---------------- helpers ----------------
__device__ __forceinline__ uint32_t smem_u32(const void* p) {
    uint32_t a;
    asm("{ .reg .u64 t; cvta.to.shared.u64 t, %1; cvt.u32.u64 %0, t; }" : "=r"(a) : "l"(p));
    return a;
}
__device__ __forceinline__ void cp16(uint32_t s, const void* g) {
    asm volatile("cp.async.cg.shared.global [%0], [%1], 16;" :: "r"(s), "l"(g) : "memory");
}
#define CP_COMMIT() asm volatile("cp.async.commit_group;" ::: "memory")

#define LDSM4(R, A) \
    asm volatile("ldmatrix.sync.aligned.m8n8.x4.shared.b16 {%0,%1,%2,%3}, [%4];" \
        : "=r"((R)[0]), "=r"((R)[1]), "=r"((R)[2]), "=r"((R)[3]) : "r"(A))

#define MMAH(D, A, B) \
    asm volatile("mma.sync.aligned.m16n8k16.row.col.f32.f16.f16.f32 " \
        "{%0,%1,%2,%3}, {%4,%5,%6,%7}, {%8,%9}, {%0,%1,%2,%3};" \
        : "+f"((D)[0]), "+f"((D)[1]), "+f"((D)[2]), "+f"((D)[3]) \
        : "r"((A)[0]), "r"((A)[1]), "r"((A)[2]), "r"((A)[3]), "r"((B)[0]), "r"((B)[1]))

// B-weight split: w = Bh + Bl/2048, Bl kept in fp16 normal range
__device__ __forceinline__ void wsplit(float v, __half& hi, __half& lo) {
    hi = __float2half(v);
    lo = __float2half((v - __half2float(hi)) * 2048.0f);
}

// SW128-style swizzle inside a 64-row x 128B tile: 16B unit XOR row%8 (B tile)
__device__ __forceinline__ uint32_t swz(int row, int unit) {
    return (uint32_t)(row * 128 + ((unit ^ (row & 7)) << 4));
}

// ------- fused prep: x->fp16 + weight transpose/split + dtype detect + scatter
__global__ void __launch_bounds__(256) prep_kernel(const float* __restrict__ x,
                                                   const float* __restrict__ W1,
                                                   const float* __restrict__ W2,
                                                   const int* __restrict__ ew) {
    const int tid = threadIdx.x;
    const int idx = blockIdx.x * 256 + tid;

    __shared__ int s_is64;
    if (tid < 32) {
        int bad = (ew[2 * tid + 1] != 0);
        unsigned m = __ballot_sync(0xffffffffu, bad);
        if (tid == 0) s_is64 = (m == 0) ? 1 : 0;
    }

    // x -> fp16: 320000 threads x 8 elements == NN*DD exactly
    {
        const float4* xf = (const float4*)x;
        float4 v0 = xf[idx * 2], v1 = xf[idx * 2 + 1];
        __half2 p0 = __floats2half2_rn(v0.x, v0.y);
        __half2 p1 = __floats2half2_rn(v0.z, v0.w);
        __half2 p2 = __floats2half2_rn(v1.x, v1.y);
        __half2 p3 = __floats2half2_rn(v1.z, v1.w);
        uint4 u;
        u.x = *(uint32_t*)&p0; u.y = *(uint32_t*)&p1;
        u.z = *(uint32_t*)&p2; u.w = *(uint32_t*)&p3;
        *(uint4*)&g_xh[idx * 8] = u;
    }

    // weight transpose + split (first 512 blocks' worth of idx)
    if (idx < 2 * DD * DD) {
        int layer = idx >> 16;
        int n = (idx >> 8) & 255;
        int k = idx & 255;
        const float* W = layer ? W2 : W1;
        float v = W[k * DD + n];
        __half hi, lo;
        wsplit(v, hi, lo);
        if (layer) { g_w2h[n * DD + k] = hi; g_w2l[n * DD + k] = lo; }
        else       { g_w1h[n * DD + k] = hi; g_w1l[n * DD + k] = lo; }
    }
    __syncthreads();

    const int f = s_is64;
    int src = f ? ew[2 * idx] : ew[idx];
    int dst = f ? ew[2 * (EE + idx)] : ew[EE + idx];
    int pos = atomicAdd(&g_deg[dst], 1);
    if (pos < SLOTS) g_sorted[dst * SLOTS + pos] = src;
}

// ------- aggregation: fp16 gathers (512B/row, half the L2 traffic) ---------
__global__ void __launch_bounds__(64) aggregate_kernel(const float* __restrict__ x) {
    int node = blockIdx.x;
    int t = threadIdx.x;
    // self term in fp32 for accuracy
    float4 acc = ((const float4*)x)[(size_t)node * D4 + t];
    int deg = min(g_deg[node], SLOTS);
    int s = node * SLOTS;
    __shared__ int srcs[SLOTS];
    for (int k = t; k < deg; k += 64) srcs[k] = g_sorted[s + k];
    __syncthreads();
    if (t == 0) g_deg[node] = 0;
    const uint2* xh = (const uint2*)g_xh;   // 64 uint2 per row
#pragma unroll 4
    for (int k = 0; k < deg; k++) {
        uint2 v = xh[(size_t)srcs[k] * 64 + t];
        float2 f0 = __half22float2(*(__half2*)&v.x);
        float2 f1 = __half22float2(*(__half2*)&v.y);
        acc.x += f0.x; acc.y += f0.y; acc.z += f1.x; acc.w += f1.y;
    }
    __half2 p0 = __floats2half2_rn(acc.x, acc.y);
    __half2 p1 = __floats2half2_rn(acc.z, acc.w);
    uint2 u;
    u.x = *(uint32_t*)&p0; u.y = *(uint32_t*)&p1;
    *(uint2*)&g_h[(size_t)node * DD + 4 * t] = u;
}

// ---------------- fp16 2-term HMMA GEMM, 3-stage + fragment pipeline -------
#define A_BYTES 5120
#define STAGE_B 13312
#define NSTG 3
#define SMEM_BYTES (NSTG * STAGE_B + 256)

template <int LAYER>
__global__ void __launch_bounds__(256, 3) gemm_mma(const float* __restrict__ bias,
                                                   float* __restrict__ out) {
    extern __shared__ char smem[];
    const uint32_t sb = smem_u32(smem);
    const int tid = threadIdx.x, wid = tid >> 5, lane = tid & 31;
    const int m0 = blockIdx.x * 64, n0 = blockIdx.y * 64;
    const int wm = wid >> 2, wn = wid & 3;   // 2m x 4n warps

    const __half* __restrict__ A  = (LAYER == 1) ? g_h   : g_h1;
    const __half* __restrict__ Bh = (LAYER == 1) ? g_w1h : g_w2h;
    const __half* __restrict__ Bl = (LAYER == 1) ? g_w1l : g_w2l;

    float* sBias = (float*)(smem + NSTG * STAGE_B);
    if (tid < 64) sBias[tid] = bias[n0 + tid];

    const int row = tid >> 2, seg = tid & 3;
    const int gma = min(m0 + row, NN - 1);
    const uint32_t sBs = swz(row, seg), sBs4 = swz(row, seg + 4);

    auto load_stage = [&](int kb, uint32_t st) {
        size_t goa = (size_t)gma * DD + kb * 32 + seg * 8;
        cp16(st + row * 80 + seg * 16, A + goa);
        size_t gob = (size_t)(n0 + row) * DD + kb * 32 + seg * 8;
        cp16(st + A_BYTES + sBs,  Bh + gob);
        cp16(st + A_BYTES + sBs4, Bl + gob);
        CP_COMMIT();
    };

    float acc[2][2][4], acc2[2][2][4];
#pragma unroll
    for (int a = 0; a < 2; a++)
#pragma unroll
        for (int b = 0; b < 2; b++)
#pragma unroll
            for (int c = 0; c < 4; c++) { acc[a][b][c] = 0.f; acc2[a][b][c] = 0.f; }

    const int bg = lane >> 3;
    const int la15 = lane & 15, la16 = lane >> 4;
    const int rA0 = wm * 32 + la15, rA1 = wm * 32 + 16 + la15;
    const int rB = wn * 16 + ((bg >> 1) << 3) + (lane & 7);

    uint32_t AH[2][2][4], BHf[2][4], BLf[2][4];

    auto ld_frags = [&](int buf, uint32_t st, int ks) {
        LDSM4(AH[buf][0], st + rA0 * 80 + ks * 32 + la16 * 16);
        LDSM4(AH[buf][1], st + rA1 * 80 + ks * 32 + la16 * 16);
        const int ub = ks * 2 + (bg & 1);
        LDSM4(BHf[buf], st + A_BYTES + swz(rB, ub));
        LDSM4(BLf[buf], st + A_BYTES + swz(rB, ub + 4));
    };
    auto do_mma = [&](int buf) {
#pragma unroll
        for (int mt = 0; mt < 2; mt++)
#pragma unroll
            for (int nt = 0; nt < 2; nt++)
                MMAH(acc[mt][nt], AH[buf][mt], (&BHf[buf][nt * 2]));
#pragma unroll
        for (int mt = 0; mt < 2; mt++)
#pragma unroll
            for (int nt = 0; nt < 2; nt++)
                MMAH(acc2[mt][nt], AH[buf][mt], (&BLf[buf][nt * 2]));
    };

    load_stage(0, sb);
    load_stage(1, sb + STAGE_B);
    asm volatile("cp.async.wait_group 1;" ::: "memory");   // stage 0 ready
    __syncthreads();
    ld_frags(0, sb, 0);
    int cur = 0;

#pragma unroll
    for (int kb = 0; kb < 8; kb++) {
        uint32_t st = sb + (kb % NSTG) * STAGE_B;
        // ---- ks = 0: issue next gmem stage, prefetch ks=1 frags
        if (kb + 2 < 8) load_stage(kb + 2, sb + ((kb + 2) % NSTG) * STAGE_B);
        ld_frags(cur ^ 1, st, 1);
        do_mma(cur);
        cur ^= 1;
        // ---- ks = 1: make stage kb+1 visible, prefetch its ks=0 frags
        if (kb < 7) {
            if (kb < 6) asm volatile("cp.async.wait_group 1;" ::: "memory");
            else        asm volatile("cp.async.wait_group 0;" ::: "memory");
            __syncthreads();   // publish stage kb+1; gates slot reuse
            ld_frags(cur ^ 1, sb + ((kb + 1) % NSTG) * STAGE_B, 0);
        }
        do_mma(cur);
        cur ^= 1;
    }

    const float SC = 1.0f / 2048.0f;
    const int gq = lane >> 2, tq = lane & 3;
#pragma unroll
    for (int mt = 0; mt < 2; mt++) {
#pragma unroll
        for (int half = 0; half < 2; half++) {
            int r = m0 + wm * 32 + mt * 16 + gq + half * 8;
            if (r >= NN) continue;
#pragma unroll
            for (int nt = 0; nt < 2; nt++) {
                int col = wn * 16 + nt * 8 + tq * 2;
                int i0 = half * 2;
                float v0 = acc[mt][nt][i0]     + acc2[mt][nt][i0]     * SC + sBias[col];
                float v1 = acc[mt][nt][i0 + 1] + acc2[mt][nt][i0 + 1] * SC + sBias[col + 1];
                size_t o = (size_t)r * DD + n0 + col;
                if (LAYER == 1) {
                    v0 = fmaxf(v0, 0.f);
                    v1 = fmaxf(v1, 0.f);
                    __half p0 = __float2half(v0), p1 = __float2half(v1);
                    *(uint32_t*)&g_h1[o] =
                        (uint32_t)__half_as_ushort(p0) | ((uint32_t)__half_as_ushort(p1) << 16);
                } else {
                    *(float2*)(out + o) = make_float2(v0, v1);
                }
            }
        }
    }
}

extern "C" void kernel_launch(void* const* d_in, const int* in_sizes, int n_in,
                              void* d_out, int out_size) {
    const float* x  = (const float*)d_in[0];
    const int*   ei = (const int*)d_in[1];
    const float* W1 = (const float*)d_in[2];
    const float* b1 = (const float*)d_in[3];
    const float* W2 = (const float*)d_in[4];
    const float* b2 = (const float*)d_in[5];
    float* out = (float*)d_out;

    cudaFuncSetAttribute(gemm_mma<1>, cudaFuncAttributeMaxDynamicSharedMemorySize, SMEM_BYTES);
    cudaFuncSetAttribute(gemm_mma<2>, cudaFuncAttributeMaxDynamicSharedMemorySize, SMEM_BYTES);

    prep_kernel<<<EE / 256, 256>>>(x, W1, W2, ei);
    aggregate_kernel<<<NN, 64>>>(x);

    dim3 grid((NN + 63) / 64, DD / 64);
    gemm_mma<1><<<grid, 256, SMEM_BYTES>>>(b1, out);
    gemm_mma<2><<<grid, 256, SMEM_BYTES>>>(b2, out);
}

// round 14
// speedup vs baseline: 1.2897x; 1.0013x over previous
#include <cuda_runtime.h>
#include <cuda_fp16.h>
#include <cstdint>

#define NN 10000
#define EE 320000
#define DD 256
#define D4 (DD / 4)
#define SLOTS 96   // deg ~ Poisson(32), P(>=96) < 1e-20

// -------- persistent device scratch (no allocations allowed) --------
__device__ __half g_xh [NN * DD];   // fp16(x) — gather source (5MB, L2-resident)
__device__ __half g_h  [NN * DD];   // fp16(x+agg)
__device__ __half g_h1 [NN * DD];   // fp16(relu(h@W1+b1))
__device__ __half g_w1 [DD * DD];   // fp16(W1^T)
__device__ __half g_w2 [DD * DD];   // fp16(W2^T)
__device__ int g_deg[NN];           // zero at load; re-zeroed by aggregate each call
__device__ int g_sorted[NN * SLOTS];

// ---------------- helpers ----------------
__device__ __forceinline__ uint32_t smem_u32(const void* p) {
    uint32_t a;
    asm("{ .reg .u64 t; cvta.to.shared.u64 t, %1; cvt.u32.u64 %0, t; }" : "=r"(a) : "l"(p));
    return a;
}
__device__ __forceinline__ void cp16(uint32_t s, const void* g) {
    asm volatile("cp.async.cg.shared.global [%0], [%1], 16;" :: "r"(s), "l"(g) : "memory");
}
#define CP_COMMIT() asm volatile("cp.async.commit_group;" ::: "memory")

#define LDSM4(R, A) \
    asm volatile("ldmatrix.sync.aligned.m8n8.x4.shared.b16 {%0,%1,%2,%3}, [%4];" \
        : "=r"((R)[0]), "=r"((R)[1]), "=r"((R)[2]), "=r"((R)[3]) : "r"(A))

#define MMAH(D, A, B) \
    asm volatile("mma.sync.aligned.m16n8k16.row.col.f32.f16.f16.f32 " \
        "{%0,%1,%2,%3}, {%4,%5,%6,%7}, {%8,%9}, {%0,%1,%2,%3};" \
        : "+f"((D)[0]), "+f"((D)[1]), "+f"((D)[2]), "+f"((D)[3]) \
        : "r"((A)[0]), "r"((A)[1]), "r"((A)[2]), "r"((A)[3]), "r"((B)[0]), "r"((B)[1]))

// ------- fused prep: x->fp16 + weight transpose + dtype detect + scatter ----
__global__ void __launch_bounds__(256) prep_kernel(const float* __restrict__ x,
                                                   const float* __restrict__ W1,
                                                   const float* __restrict__ W2,
                                                   const int* __restrict__ ew) {
    const int tid = threadIdx.x;
    const int idx = blockIdx.x * 256 + tid;

    __shared__ int s_is64;
    if (tid < 32) {
        int bad = (ew[2 * tid + 1] != 0);
        unsigned m = __ballot_sync(0xffffffffu, bad);
        if (tid == 0) s_is64 = (m == 0) ? 1 : 0;
    }

    // x -> fp16: 320000 threads x 8 elements == NN*DD exactly
    {
        const float4* xf = (const float4*)x;
        float4 v0 = xf[idx * 2], v1 = xf[idx * 2 + 1];
        __half2 p0 = __floats2half2_rn(v0.x, v0.y);
        __half2 p1 = __floats2half2_rn(v0.z, v0.w);
        __half2 p2 = __floats2half2_rn(v1.x, v1.y);
        __half2 p3 = __floats2half2_rn(v1.z, v1.w);
        uint4 u;
        u.x = *(uint32_t*)&p0; u.y = *(uint32_t*)&p1;
        u.z = *(uint32_t*)&p2; u.w = *(uint32_t*)&p3;
        *(uint4*)&g_xh[idx * 8] = u;
    }

    // weight transpose -> fp16 (first 512 blocks' worth of idx)
    if (idx < 2 * DD * DD) {
        int layer = idx >> 16;
        int n = (idx >> 8) & 255;
        int k = idx & 255;
        const float* W = layer ? W2 : W1;
        __half v = __float2half(W[k * DD + n]);
        if (layer) g_w2[n * DD + k] = v;
        else       g_w1[n * DD + k] = v;
    }
    __syncthreads();

    const int f = s_is64;
    int src = f ? ew[2 * idx] : ew[idx];
    int dst = f ? ew[2 * (EE + idx)] : ew[EE + idx];
    int pos = atomicAdd(&g_deg[dst], 1);
    if (pos < SLOTS) g_sorted[dst * SLOTS + pos] = src;
}

// ------- aggregation: fp16 gathers; self term fp32; re-zeros g_deg ---------
__global__ void __launch_bounds__(64) aggregate_kernel(const float* __restrict__ x) {
    int node = blockIdx.x;
    int t = threadIdx.x;
    float4 acc = ((const float4*)x)[(size_t)node * D4 + t];
    int deg = min(g_deg[node], SLOTS);
    int s = node * SLOTS;
    __shared__ int srcs[SLOTS];
    for (int k = t; k < deg; k += 64) srcs[k] = g_sorted[s + k];
    __syncthreads();
    if (t == 0) g_deg[node] = 0;
    const uint2* xh = (const uint2*)g_xh;   // 64 uint2 per row
#pragma unroll 4
    for (int k = 0; k < deg; k++) {
        uint2 v = xh[(size_t)srcs[k] * 64 + t];
        float2 f0 = __half22float2(*(__half2*)&v.x);
        float2 f1 = __half22float2(*(__half2*)&v.y);
        acc.x += f0.x; acc.y += f0.y; acc.z += f1.x; acc.w += f1.y;
    }
    __half2 p0 = __floats2half2_rn(acc.x, acc.y);
    __half2 p1 = __floats2half2_rn(acc.z, acc.w);
    uint2 u;
    u.x = *(uint32_t*)&p0; u.y = *(uint32_t*)&p1;
    *(uint2*)&g_h[(size_t)node * DD + 4 * t] = u;
}

// ---------------- plain fp16 HMMA GEMM, 3-stage + fragment pipeline --------
// C = A@B + bias, fp32 accum. 4 MMA + 3 LDSM per phase. A and B tiles both
// use the 80B-stride conflict-free layout (banks (r*5+u) mod 8 cover all 8
// across any ldmatrix 8-row phase). Stage = 2*5120B; 3 stages; 4 CTAs/SM.
#define A_BYTES 5120
#define STAGE_B 10240
#define NSTG 3
#define SMEM_BYTES (NSTG * STAGE_B + 256)

template <int LAYER>
__global__ void __launch_bounds__(256, 4) gemm_mma(const float* __restrict__ bias,
                                                   float* __restrict__ out) {
    extern __shared__ char smem[];
    const uint32_t sb = smem_u32(smem);
    const int tid = threadIdx.x, wid = tid >> 5, lane = tid & 31;
    const int m0 = blockIdx.x * 64, n0 = blockIdx.y * 64;
    const int wm = wid >> 2, wn = wid & 3;   // 2m x 4n warps

    const __half* __restrict__ A = (LAYER == 1) ? g_h  : g_h1;
    const __half* __restrict__ B = (LAYER == 1) ? g_w1 : g_w2;

    float* sBias = (float*)(smem + NSTG * STAGE_B);
    if (tid < 64) sBias[tid] = bias[n0 + tid];

    const int row = tid >> 2, seg = tid & 3;
    const int gma = min(m0 + row, NN - 1);
    const uint32_t sOff = row * 80 + seg * 16;

    auto load_stage = [&](int kb, uint32_t st) {
        size_t goa = (size_t)gma * DD + kb * 32 + seg * 8;
        cp16(st + sOff, A + goa);
        size_t gob = (size_t)(n0 + row) * DD + kb * 32 + seg * 8;
        cp16(st + A_BYTES + sOff, B + gob);
        CP_COMMIT();
    };

    float acc[2][2][4];
#pragma unroll
    for (int a = 0; a < 2; a++)
#pragma unroll
        for (int b = 0; b < 2; b++)
#pragma unroll
            for (int c = 0; c < 4; c++) acc[a][b][c] = 0.f;

    const int bg = lane >> 3;
    const int la15 = lane & 15, la16 = lane >> 4;
    const int rA0 = wm * 32 + la15, rA1 = wm * 32 + 16 + la15;
    const int rB = wn * 16 + ((bg >> 1) << 3) + (lane & 7);

    uint32_t AH[2][2][4], BF[2][4];

    auto ld_frags = [&](int buf, uint32_t st, int ks) {
        LDSM4(AH[buf][0], st + rA0 * 80 + ks * 32 + la16 * 16);
        LDSM4(AH[buf][1], st + rA1 * 80 + ks * 32 + la16 * 16);
        LDSM4(BF[buf], st + A_BYTES + rB * 80 + (ks * 2 + (bg & 1)) * 16);
    };
    auto do_mma = [&](int buf) {
#pragma unroll
        for (int mt = 0; mt < 2; mt++)
#pragma unroll
            for (int nt = 0; nt < 2; nt++)
                MMAH(acc[mt][nt], AH[buf][mt], (&BF[buf][nt * 2]));
    };

    load_stage(0, sb);
    load_stage(1, sb + STAGE_B);
    asm volatile("cp.async.wait_group 1;" ::: "memory");   // stage 0 ready
    __syncthreads();
    ld_frags(0, sb, 0);
    int cur = 0;

#pragma unroll
    for (int kb = 0; kb < 8; kb++) {
        uint32_t st = sb + (kb % NSTG) * STAGE_B;
        // ---- ks = 0: issue next gmem stage, prefetch ks=1 frags
        if (kb + 2 < 8) load_stage(kb + 2, sb + ((kb + 2) % NSTG) * STAGE_B);
        ld_frags(cur ^ 1, st, 1);
        do_mma(cur);
        cur ^= 1;
        // ---- ks = 1: make stage kb+1 visible, prefetch its ks=0 frags
        if (kb < 7) {
            if (kb < 6) asm volatile("cp.async.wait_group 1;" ::: "memory");
            else        asm volatile("cp.async.wait_group 0;" ::: "memory");
            __syncthreads();   // publish stage kb+1; gates slot reuse
            ld_frags(cur ^ 1, sb + ((kb + 1) % NSTG) * STAGE_B, 0);
        }
        do_mma(cur);
        cur ^= 1;
    }

    const int gq = lane >> 2, tq = lane & 3;
#pragma unroll
    for (int mt = 0; mt < 2; mt++) {
#pragma unroll
        for (int half = 0; half < 2; half++) {
            int r = m0 + wm * 32 + mt * 16 + gq + half * 8;
            if (r >= NN) continue;
#pragma unroll
            for (int nt = 0; nt < 2; nt++) {
                int col = wn * 16 + nt * 8 + tq * 2;
                int i0 = half * 2;
                float v0 = acc[mt][nt][i0]     + sBias[col];
                float v1 = acc[mt][nt][i0 + 1] + sBias[col + 1];
                size_t o = (size_t)r * DD + n0 + col;
                if (LAYER == 1) {
                    v0 = fmaxf(v0, 0.f);
                    v1 = fmaxf(v1, 0.f);
                    __half p0 = __float2half(v0), p1 = __float2half(v1);
                    *(uint32_t*)&g_h1[o] =
                        (uint32_t)__half_as_ushort(p0) | ((uint32_t)__half_as_ushort(p1) << 16);
                } else {
                    *(float2*)(out + o) = make_float2(v0, v1);
                }
            }
        }
    }
}

extern "C" void kernel_launch(void* const* d_in, const int* in_sizes, int n_in,
                              void* d_out, int out_size) {
    const float* x  = (const float*)d_in[0];
    const int*   ei = (const int*)d_in[1];
    const float* W1 = (const float*)d_in[2];
    const float* b1 = (const float*)d_in[3];
    const float* W2 = (const float*)d_in[4];
    const float* b2 = (const float*)d_in[5];
    float* out = (float*)d_out;

    cudaFuncSetAttribute(gemm_mma<1>, cudaFuncAttributeMaxDynamicSharedMemorySize, SMEM_BYTES);
    cudaFuncSetAttribute(gemm_mma<2>, cudaFuncAttributeMaxDynamicSharedMemorySize, SMEM_BYTES);

    prep_kernel<<<EE / 256, 256>>>(x, W1, W2, ei);
    aggregate_kernel<<<NN, 64>>>(x);

    dim3 grid((NN + 63) / 64, DD / 64);
    gemm_mma<1><<<grid, 256, SMEM_BYTES>>>(b1, out);
    gemm_mma<2><<<grid, 256, SMEM_BYTES>>>(b2, out);
}